// round 8
// baseline (speedup 1.0000x reference)
#include <cuda_runtime.h>
#include <cuda_fp16.h>
#include <cuda_bf16.h>

// Problem constants (fixed by the dataset)
#define Bc   4
#define Cc   16
#define Hc   256
#define Wc   256
#define HWc  (Hc * Wc)
#define Coc  16
#define Kc   9
#define INV_N (1.0f / (float)(Bc * Coc * HWc))

// Tiling: 32x16 pixel tile, 256 threads (8 warps), 2 pixels/thread (rows r, r+8)
#define TILE_W 32
#define TILE_H 16
#define PAD    6
#define ROWS   (TILE_H + 2 * PAD)     // 28
#define COLS   (TILE_W + 2 * PAD)     // 44
#define NSITES (ROWS * COLS)          // 1232
#define SITE_U4 3                     // 48B per site: 16 fp16 ch + 8 pad halves
#define SIN_BYTES   (NSITES * SITE_U4 * 16)   // 59136

// Per-warp A-tile: 64 pixel-rows x 16 halves, 48B row stride (conflict-free STS/LDSM)
#define AT_ROW_BYTES 48
#define AT_WARP_BYTES (64 * AT_ROW_BYTES)     // 3072
#define SAT_OFF  SIN_BYTES                    // 59136
#define SBF_OFF  (SAT_OFF + 8 * AT_WARP_BYTES)  // 83712
#define NBF      (Kc * 2 * 32)                // 576 uint2 B-fragments
#define SMEM_BYTES (SBF_OFF + NBF * 8)        // 88320

__global__ void zero_out_kernel(float* out) {
    if (threadIdx.x == 0) out[0] = 0.0f;
}

__device__ __forceinline__ unsigned smem_u32(const void* p) {
    unsigned a;
    asm("{ .reg .u64 t; cvta.to.shared.u64 t, %1; cvt.u32.u64 %0, t; }" : "=r"(a) : "l"(p));
    return a;
}

__device__ __forceinline__ void ldsm_x4(unsigned& a0, unsigned& a1, unsigned& a2, unsigned& a3,
                                        unsigned addr) {
    asm volatile("ldmatrix.sync.aligned.m8n8.x4.shared.b16 {%0,%1,%2,%3}, [%4];"
                 : "=r"(a0), "=r"(a1), "=r"(a2), "=r"(a3) : "r"(addr));
}

__device__ __forceinline__ void mma16816(float* d,
                                         unsigned a0, unsigned a1, unsigned a2, unsigned a3,
                                         unsigned b0, unsigned b1) {
    asm volatile("mma.sync.aligned.m16n8k16.row.col.f32.f16.f16.f32 "
                 "{%0,%1,%2,%3}, {%4,%5,%6,%7}, {%8,%9}, {%0,%1,%2,%3};"
                 : "+f"(d[0]), "+f"(d[1]), "+f"(d[2]), "+f"(d[3])
                 : "r"(a0), "r"(a1), "r"(a2), "r"(a3), "r"(b0), "r"(b1));
}

extern __shared__ char smemc[];

__global__ __launch_bounds__(256, 2) void dcn_loss_kernel(
    const float* __restrict__ offsets,  // [B, 18, H, W]
    const float* __restrict__ input,    // [B, 16, H, W]
    const float* __restrict__ ker,      // [16, 16, 3, 3]
    const float* __restrict__ target,   // [B, 16, H, W]
    float* __restrict__ out)
{
    const int tid = threadIdx.x;
    const int b   = blockIdx.z;
    const int rowBase = blockIdx.y * TILE_H;
    const int colBase = blockIdx.x * TILE_W;
    const int rowLo = rowBase - PAD;
    const int colLo = colBase - PAD;

    const float* inB = input + b * Cc * HWc;
    uint4* sIn = (uint4*)smemc;                 // input tile, 3 uint4/site
    uint2* sBF = (uint2*)(smemc + SBF_OFF);     // B fragments per (kk, ntile, lane)

    // ---- Stage input tile as fp16, site-major, 48B stride (zeros outside) ----
    for (int i = tid; i < NSITES; i += 256) {
        const int ry = i / COLS;
        const int rx = i - ry * COLS;
        const int gy = rowLo + ry;
        const int gx = colLo + rx;
        const bool ok = ((unsigned)gy < Hc) && ((unsigned)gx < Wc);
        const float* src = inB + gy * Wc + gx;
        __half2 h[8];
        #pragma unroll
        for (int j = 0; j < 8; j++) {
            float v0 = ok ? __ldg(src + (2 * j) * HWc)     : 0.0f;
            float v1 = ok ? __ldg(src + (2 * j + 1) * HWc) : 0.0f;
            h[j] = __floats2half2_rn(v0, v1);
        }
        sIn[SITE_U4 * i]     = *(const uint4*)&h[0];
        sIn[SITE_U4 * i + 1] = *(const uint4*)&h[4];
    }

    // ---- Stage B fragments: b-frag for (kk, ntile, lane) ----
    // B[k][n] = ker[o = g+8*nt][c = k][kk];  b0=(B[2t],B[2t+1]), b1=(B[2t+8],B[2t+9]) at col g
    for (int i = tid; i < NBF; i += 256) {
        const int lane = i & 31;
        const int nt   = (i >> 5) & 1;
        const int kk   = i >> 6;
        const int t = lane & 3;
        const int g = lane >> 2;
        const int o = g + 8 * nt;
        const float* kb = ker + o * (Cc * Kc) + kk;    // index by + c*Kc
        const __half2 b0 = __floats2half2_rn(kb[(2 * t)     * Kc], kb[(2 * t + 1) * Kc]);
        const __half2 b1 = __floats2half2_rn(kb[(2 * t + 8) * Kc], kb[(2 * t + 9) * Kc]);
        uint2 u;
        u.x = *(const unsigned*)&b0;
        u.y = *(const unsigned*)&b1;
        sBF[i] = u;
    }
    __syncthreads();

    // ---- Warp/pixel mapping: warp w covers rows (rowBase+w, rowBase+w+8) x 32 cols ----
    const int lane   = tid & 31;
    const int warpId = tid >> 5;
    const int wpx    = colBase + lane;
    const int t4 = lane & 3;
    const int g8 = lane >> 2;

    int hpx[2], hw[2];
    #pragma unroll
    for (int p = 0; p < 2; p++) {
        hpx[p] = rowBase + warpId + 8 * p;
        hw[p]  = hpx[p] * Wc + wpx;
    }
    const float* offBase = offsets + b * 2 * Kc * HWc;
    const float* tgtBase = target  + b * Coc * HWc;

    // A-tile addresses
    char* aWarp = smemc + SAT_OFF + warpId * AT_WARP_BYTES;
    uint4* aRow[2];
    #pragma unroll
    for (int p = 0; p < 2; p++)
        aRow[p] = (uint4*)(aWarp + (p * 32 + lane) * AT_ROW_BYTES);
    unsigned aTileAddr[4];
    {
        const unsigned aBase = smem_u32(aWarp);
        #pragma unroll
        for (int tile = 0; tile < 4; tile++)
            aTileAddr[tile] = aBase + (tile * 16 + (lane & 15)) * AT_ROW_BYTES
                            + (lane >> 4) * 16;
    }

    // Accumulators: 4 m16-tiles x 2 n8-tiles x 4 fp32
    float acc[4][2][4];
    #pragma unroll
    for (int tl = 0; tl < 4; tl++)
        #pragma unroll
        for (int nt = 0; nt < 2; nt++)
            #pragma unroll
            for (int j = 0; j < 4; j++) acc[tl][nt][j] = 0.0f;

    // Fast-path sampler: bilinear in packed half2 -> sv[8] = (ch2j, ch2j+1)
    auto sample16h = [&](int site, float wy, float wx, __half2* sv) {
        const __half2 h00 = __float2half2_rn((1.0f - wy) * (1.0f - wx));
        const __half2 h01 = __float2half2_rn((1.0f - wy) * wx);
        const __half2 h10 = __float2half2_rn(wy * (1.0f - wx));
        const __half2 h11 = __float2half2_rn(wy * wx);
        const uint4* p = sIn + SITE_U4 * site;
        #pragma unroll
        for (int chunk = 0; chunk < 2; chunk++) {
            const uint4 a00 = p[chunk];
            const uint4 a01 = p[SITE_U4 + chunk];
            const uint4 a10 = p[SITE_U4 * COLS + chunk];
            const uint4 a11 = p[SITE_U4 * COLS + SITE_U4 + chunk];
            const __half2* c00 = (const __half2*)&a00;
            const __half2* c01 = (const __half2*)&a01;
            const __half2* c10 = (const __half2*)&a10;
            const __half2* c11 = (const __half2*)&a11;
            #pragma unroll
            for (int j = 0; j < 4; j++) {
                __half2 v = __hmul2(c00[j], h00);
                v = __hfma2(c01[j], h01, v);
                v = __hfma2(c10[j], h10, v);
                v = __hfma2(c11[j], h11, v);
                sv[chunk * 4 + j] = v;
            }
        }
    };

    // Rare exact fallback: fp32 global gather -> sv[8]
    auto sample_generic = [&](float y, float x, __half2* sv) {
        const float y0f = floorf(y), x0f = floorf(x);
        const float wy = y - y0f, wx = x - x0f;
        const int y0 = (int)y0f, x0 = (int)x0f;
        const int y1 = y0 + 1, x1 = x0 + 1;
        const bool vy0 = ((unsigned)y0 < Hc), vy1 = ((unsigned)y1 < Hc);
        const bool vx0 = ((unsigned)x0 < Wc), vx1 = ((unsigned)x1 < Wc);
        const float w00 = (1.0f - wy) * (1.0f - wx) * (float)(vy0 && vx0);
        const float w01 = (1.0f - wy) * wx          * (float)(vy0 && vx1);
        const float w10 = wy          * (1.0f - wx) * (float)(vy1 && vx0);
        const float w11 = wy          * wx          * (float)(vy1 && vx1);
        const int cy0 = min(max(y0, 0), Hc - 1), cy1 = min(max(y1, 0), Hc - 1);
        const int cx0 = min(max(x0, 0), Wc - 1), cx1 = min(max(x1, 0), Wc - 1);
        const int i00 = cy0 * Wc + cx0, i01 = cy0 * Wc + cx1;
        const int i10 = cy1 * Wc + cx0, i11 = cy1 * Wc + cx1;
        #pragma unroll
        for (int cj = 0; cj < 8; cj++) {
            float s[2];
            #pragma unroll
            for (int u = 0; u < 2; u++) {
                const float* ic = inB + (2 * cj + u) * HWc;
                s[u] = w00 * __ldg(ic + i00) + w01 * __ldg(ic + i01)
                     + w10 * __ldg(ic + i10) + w11 * __ldg(ic + i11);
            }
            sv[cj] = __floats2half2_rn(s[0], s[1]);
        }
    };

    for (int kk = 0; kk < Kc; kk++) {
        const int kr = kk / 3;
        const int kc = kk - 3 * kr;

        // Sample both pixels and store rows into the warp A-tile
        #pragma unroll
        for (int p = 0; p < 2; p++) {
            const float dy = __ldg(offBase + (2 * kk) * HWc + hw[p]);
            const float dx = __ldg(offBase + (2 * kk + 1) * HWc + hw[p]);
            const float y = dy + (float)(hpx[p] - 1 + kr);
            const float x = dx + (float)(wpx - 1 + kc);
            const float y0f = floorf(y), x0f = floorf(x);
            const int ry0 = (int)y0f - rowLo;
            const int rx0 = (int)x0f - colLo;

            __half2 sv[8];
            if (((unsigned)ry0 <= (ROWS - 2)) && ((unsigned)rx0 <= (COLS - 2)))
                sample16h(ry0 * COLS + rx0, y - y0f, x - x0f, sv);
            else
                sample_generic(y, x, sv);

            aRow[p][0] = *(const uint4*)&sv[0];
            aRow[p][1] = *(const uint4*)&sv[4];
        }
        __syncwarp();

        // B fragments for this kk
        const uint2 bf0 = sBF[(kk * 2 + 0) * 32 + lane];
        const uint2 bf1 = sBF[(kk * 2 + 1) * 32 + lane];

        // 4 m16-tiles x 2 n8-tiles
        #pragma unroll
        for (int tile = 0; tile < 4; tile++) {
            unsigned a0, a1, a2, a3;
            ldsm_x4(a0, a1, a2, a3, aTileAddr[tile]);
            mma16816(acc[tile][0], a0, a1, a2, a3, bf0.x, bf0.y);
            mma16816(acc[tile][1], a0, a1, a2, a3, bf1.x, bf1.y);
        }
        __syncwarp();   // protect A-tile WAR before next kk's stores
    }

    // ---- Loss epilogue: D-frag -> (pixel, output), squared error ----
    float local = 0.0f;
    #pragma unroll
    for (int tile = 0; tile < 4; tile++) {
        #pragma unroll
        for (int half = 0; half < 2; half++) {
            const int row = tile * 16 + g8 + 8 * half;    // A-tile pixel row
            const int p   = row >> 5;
            const int lp  = row & 31;
            const int h   = rowBase + warpId + 8 * p;
            const int wv  = colBase + lp;
            const float* tg = tgtBase + h * Wc + wv;
            #pragma unroll
            for (int nt = 0; nt < 2; nt++) {
                const int o0 = nt * 8 + 2 * t4;
                const float d0 = acc[tile][nt][half * 2 + 0] - __ldg(tg + o0 * HWc);
                const float d1 = acc[tile][nt][half * 2 + 1] - __ldg(tg + (o0 + 1) * HWc);
                local += d0 * d0 + d1 * d1;
            }
        }
    }

    // ---- Warp + block reduce, one atomic per block ----
    #pragma unroll
    for (int s = 16; s > 0; s >>= 1)
        local += __shfl_xor_sync(0xFFFFFFFFu, local, s);

    __shared__ float red[8];
    if (lane == 0) red[warpId] = local;
    __syncthreads();
    if (tid < 8) {
        float v = red[tid];
        #pragma unroll
        for (int s = 4; s > 0; s >>= 1)
            v += __shfl_xor_sync(0xFFu, v, s);
        if (tid == 0) atomicAdd(out, v * INV_N);
    }
}

extern "C" void kernel_launch(void* const* d_in, const int* in_sizes, int n_in,
                              void* d_out, int out_size) {
    const float* offsets = (const float*)d_in[0];
    const float* input   = (const float*)d_in[1];
    const float* ker     = (const float*)d_in[2];
    const float* target  = (const float*)d_in[3];
    float* out = (float*)d_out;

    static bool attr_set = false;
    if (!attr_set) {
        cudaFuncSetAttribute(dcn_loss_kernel,
                             cudaFuncAttributeMaxDynamicSharedMemorySize,
                             SMEM_BYTES);
        attr_set = true;
    }

    zero_out_kernel<<<1, 32>>>(out);

    dim3 grid(Wc / TILE_W, Hc / TILE_H, Bc);   // 8 x 16 x 4 = 512 blocks
    dcn_loss_kernel<<<grid, 256, SMEM_BYTES>>>(offsets, input, ker, target, out);
}